// round 8
// baseline (speedup 1.0000x reference)
#include <cuda_runtime.h>
#include <math.h>

#define NN 50000          // N_NODES == M_NODES
#define KNBR 32
#define F 128
#define WSIZE 3
#define RPB 32            // rows per block (4 warps x 8 rows)

typedef unsigned long long ull;

// Scratch (device globals: allocation-free per harness rules)
__device__ float g_h[(size_t)NN * F];     // h = input @ W  (fp32)
__device__ float g_hc1[NN];               // fl32( fp64-accurate h . c1 )
__device__ float g_hc2[NN];               // fl32( fp64-accurate h . c2 )

// ---- packed f32x2 helpers ----
static __device__ __forceinline__ ull pack2(float lo, float hi) {
    ull r;
    asm("mov.b64 %0, {%1, %2};" : "=l"(r) : "f"(lo), "f"(hi));
    return r;
}
static __device__ __forceinline__ void unpack2(ull v, float& lo, float& hi) {
    asm("mov.b64 {%0, %1}, %2;" : "=f"(lo), "=f"(hi) : "l"(v));
}
static __device__ __forceinline__ void ffma2(ull& d, ull a, ull b) {
    asm("fma.rn.f32x2 %0, %1, %2, %0;" : "+l"(d) : "l"(a), "l"(b));
}

// ============================================================================
// Kernel A: h = input @ W (fp32, f32x2 FMA).
// ARITHMETIC CONTRACT (bitwise, frozen since R4/R6): for each (row, col),
//   acc.lo = sum over even k in ascending order of in[k]*W[k][c]
//   acc.hi = sum over odd  k in ascending order
//   h      = acc.lo + acc.hi
// followed by fp64 hc1/hc2 dots with xor-tree shfl reduction.
// This round only restructures the schedule: 8 rows/warp (halves W traffic
// and pack amortization) and input pairs loaded directly as ull from smem
// (same bits as pack2(s[k], s[k+1]) — no MOVs).
// block = 128 threads (4 warps), 32 rows/block, 4 cols/lane.
// ============================================================================
__global__ void __launch_bounds__(128) gemm_hc_kernel(
    const float* __restrict__ inp,
    const float* __restrict__ W,
    const float* __restrict__ c1,
    const float* __restrict__ c2)
{
    __shared__ float s_in[RPB][F];   // 16 KB

    const int tid  = threadIdx.x;
    const int lane = tid & 31;
    const int warp = tid >> 5;
    const int row0 = blockIdx.x * RPB;

    // stage 32 input rows (4096 floats = 1024 float4; 8 per thread)
    #pragma unroll
    for (int i = 0; i < 8; i++) {
        const int idx   = tid + i * 128;       // 0..1023
        const int row   = idx >> 5;            // 0..31
        const int chunk = idx & 31;            // 0..31
        int grow = row0 + row;
        if (grow >= NN) grow = NN - 1;         // clamp (tail block)
        ((float4*)&s_in[row][0])[chunk] =
            ((const float4*)(inp + (size_t)grow * F))[chunk];
    }
    __syncthreads();

    ull acc[8][4];
    #pragma unroll
    for (int r = 0; r < 8; r++)
        #pragma unroll
        for (int i = 0; i < 4; i++)
            acc[r][i] = 0ULL;

    const int colbase = lane * 4;
    const int rbase   = warp * 8;

    #pragma unroll 8
    for (int k = 0; k < F; k += 2) {
        const float4 wa = *(const float4*)(W + (size_t)k * F + colbase);
        const float4 wb = *(const float4*)(W + (size_t)(k + 1) * F + colbase);
        const ull wp0 = pack2(wa.x, wb.x);
        const ull wp1 = pack2(wa.y, wb.y);
        const ull wp2 = pack2(wa.z, wb.z);
        const ull wp3 = pack2(wa.w, wb.w);
        #pragma unroll
        for (int r = 0; r < 8; r++) {
            // (s_in[k], s_in[k+1]) as one 8-byte load — same bits as pack2
            const ull ip = *(const ull*)&s_in[rbase + r][k];
            ffma2(acc[r][0], ip, wp0);
            ffma2(acc[r][1], ip, wp1);
            ffma2(acc[r][2], ip, wp2);
            ffma2(acc[r][3], ip, wp3);
        }
    }

    const float4 cv1 = *(const float4*)(c1 + colbase);
    const float4 cv2 = *(const float4*)(c2 + colbase);

    #pragma unroll
    for (int r = 0; r < 8; r++) {
        float4 hv;
        float lo, hi;
        unpack2(acc[r][0], lo, hi); hv.x = lo + hi;
        unpack2(acc[r][1], lo, hi); hv.y = lo + hi;
        unpack2(acc[r][2], lo, hi); hv.z = lo + hi;
        unpack2(acc[r][3], lo, hi); hv.w = lo + hi;

        const int row = row0 + rbase + r;
        if (row < NN)
            *(float4*)(g_h + (size_t)row * F + colbase) = hv;

        // hc dot products in FP64 (accurate), stored as fp32
        double d1 = (double)hv.x * (double)cv1.x + (double)hv.y * (double)cv1.y
                  + (double)hv.z * (double)cv1.z + (double)hv.w * (double)cv1.w;
        double d2 = (double)hv.x * (double)cv2.x + (double)hv.y * (double)cv2.y
                  + (double)hv.z * (double)cv2.z + (double)hv.w * (double)cv2.w;
        #pragma unroll
        for (int off = 16; off > 0; off >>= 1) {
            d1 += __shfl_down_sync(0xffffffffu, d1, off);
            d2 += __shfl_down_sync(0xffffffffu, d2, off);
        }
        if (lane == 0 && row < NN) {
            g_hc1[row] = (float)d1;
            g_hc2[row] = (float)d2;
        }
    }
}

// ============================================================================
// Kernel B: per-node attention (one warp per node; lane j = neighbor j).
// Decision chain emulates the reference fp32 arithmetic (frozen since R6).
// ============================================================================
__global__ void __launch_bounds__(256) attn_kernel(
    const int* __restrict__ adj,
    const int* __restrict__ deg,
    float* __restrict__ out)
{
    __shared__ float s_buf[8][KNBR];

    const unsigned FULL = 0xffffffffu;
    const int warp = threadIdx.x >> 5;
    const int lane = threadIdx.x & 31;
    const int m    = blockIdx.x * 8 + warp;   // 6250 * 8 == 50000 exactly

    const int  d     = deg[m];
    const int  a     = adj[(size_t)m * KNBR + lane];
    const bool valid = (lane < d);

    const float NEG_INF = __int_as_float(0xff800000u);

    float e32 = NEG_INF;
    if (valid) {
        const float x = g_hc1[m] + g_hc2[a];   // fp32 add, as reference
        e32 = (x >= 0.f) ? x : 0.2f * x;
    }

    // max (exact, order-independent)
    float mx = e32;
    #pragma unroll
    for (int off = 16; off > 0; off >>= 1)
        mx = fmaxf(mx, __shfl_xor_sync(FULL, mx, off));

    // expf: libdevice exp, ulp-level match to the reference's exp
    const float p = valid ? expf(e32 - mx) : 0.f;

    // ---- pass 1: sequential fp32 sum of p (same order as ref reduce) ----
    s_buf[warp][lane] = p;
    __syncwarp();
    float s = 0.f;
    #pragma unroll
    for (int q = 0; q < 8; q++) {
        const float4 v = *(const float4*)&s_buf[warp][q * 4];
        s += v.x; s += v.y; s += v.z; s += v.w;
    }

    const float att = p / s;   // fp32 divide, as reference

    // ---- pass 2: sequential fp32 prefix sum with capture-at-index ----
    __syncwarp();
    s_buf[warp][lane] = att;
    __syncwarp();
    float run = 0.f, csum = 0.f, shifted = 0.f;
    const int lm3 = lane - WSIZE;
    #pragma unroll
    for (int q = 0; q < 8; q++) {
        const float4 v = *(const float4*)&s_buf[warp][q * 4];
        const int k0 = q * 4;
        run += v.x; if (k0 + 0 == lane) csum = run; if (k0 + 0 == lm3) shifted = run;
        run += v.y; if (k0 + 1 == lane) csum = run; if (k0 + 1 == lm3) shifted = run;
        run += v.z; if (k0 + 2 == lane) csum = run; if (k0 + 2 == lm3) shifted = run;
        run += v.w; if (k0 + 3 == lane) csum = run; if (k0 + 3 == lm3) shifted = run;
    }

    // win = csum - csum_shifted_by_3 (fp32, same cancellation as reference);
    // shifted == 0 for lane < 3, matching the reference's zero-padding.
    float win = -1.0f;
    if (lane >= WSIZE - 1 && lane < d)
        win = csum - shifted;

    // argmax, first occurrence on ties (np.argmax semantics)
    float bw = win;
    int   bj = lane;
    #pragma unroll
    for (int off = 16; off > 0; off >>= 1) {
        const float ow = __shfl_down_sync(FULL, bw, off);
        const int   oj = __shfl_down_sync(FULL, bj, off);
        if (ow > bw || (ow == bw && oj < bj)) { bw = ow; bj = oj; }
    }
    const int jstar = __shfl_sync(FULL, bj, 0);   // jstar >= 2 always (deg >= 3)

    const float scale = (float)d / 3.0f;
    const float t = (lane >= jstar - (WSIZE - 1) && lane <= jstar) ? att * scale : 0.f;

    // broadcast the 3 surviving (neighbor, weight) pairs (ascending k order)
    const float w0 = __shfl_sync(FULL, t, jstar - 2);
    const float w1 = __shfl_sync(FULL, t, jstar - 1);
    const float w2 = __shfl_sync(FULL, t, jstar);
    const int   a0 = __shfl_sync(FULL, a, jstar - 2);
    const int   a1 = __shfl_sync(FULL, a, jstar - 1);
    const int   a2 = __shfl_sync(FULL, a, jstar);

    // gather 3 h rows (512 B each, L2-resident), fp32 FMA chain, elu
    const float4 v0 = ((const float4*)(g_h + (size_t)a0 * F))[lane];
    const float4 v1 = ((const float4*)(g_h + (size_t)a1 * F))[lane];
    const float4 v2 = ((const float4*)(g_h + (size_t)a2 * F))[lane];

    float4 o;
    o.x = fmaf(w2, v2.x, fmaf(w1, v1.x, w0 * v0.x));
    o.y = fmaf(w2, v2.y, fmaf(w1, v1.y, w0 * v0.y));
    o.z = fmaf(w2, v2.z, fmaf(w1, v1.z, w0 * v0.z));
    o.w = fmaf(w2, v2.w, fmaf(w1, v1.w, w0 * v0.w));

    o.x = (o.x > 0.f) ? o.x : expm1f(o.x);
    o.y = (o.y > 0.f) ? o.y : expm1f(o.y);
    o.z = (o.z > 0.f) ? o.z : expm1f(o.z);
    o.w = (o.w > 0.f) ? o.w : expm1f(o.w);

    ((float4*)out)[(size_t)m * (F / 4) + lane] = o;
}

extern "C" void kernel_launch(void* const* d_in, const int* in_sizes, int n_in,
                              void* d_out, int out_size) {
    const float* inp = (const float*)d_in[0];
    const float* W   = (const float*)d_in[1];
    const float* c1  = (const float*)d_in[2];
    const float* c2  = (const float*)d_in[3];
    const int*   adj = (const int*)d_in[4];
    const int*   deg = (const int*)d_in[5];
    float*       out = (float*)d_out;

    gemm_hc_kernel<<<(NN + RPB - 1) / RPB, 128>>>(inp, W, c1, c2);  // 1563 blocks
    attn_kernel<<<NN / 8, 256>>>(adj, deg, out);                    // 6250 blocks
}